// round 16
// baseline (speedup 1.0000x reference)
#include <cuda_runtime.h>
#include <cstdint>

// Fixed shapes: B=2048, L=200, D=128, A=64
#define DD 128
#define AA 64
#define LL 200
#define BB 2048
#define NEGINF (-4294967295.0f)
#define FNEGINF __int_as_float(0xff800000)

typedef unsigned long long ull;

__device__ __forceinline__ ull pk2(float lo, float hi) {
    ull r; asm("mov.b64 %0,{%1,%2};" : "=l"(r) : "f"(lo), "f"(hi)); return r;
}
__device__ __forceinline__ void upk2(ull v, float& lo, float& hi) {
    asm("mov.b64 {%0,%1},%2;" : "=f"(lo), "=f"(hi) : "l"(v));
}
__device__ __forceinline__ ull ffma2(ull a, ull b, ull c) {
    ull d; asm("fma.rn.f32x2 %0,%1,%2,%3;" : "=l"(d) : "l"(a), "l"(b), "l"(c)); return d;
}

// ---- device scratch (module-load allocation; no runtime alloc) ----
__device__ float g_Wc[(size_t)BB * 8192];   // per-batch combined W1 [128][64]
__device__ float g_qc[(size_t)BB * 64];     // per-batch qc (b1 + q-part)

// ---- din_main smem layout (float offsets) ----
#define F_WC   0          // Wc [128][64]            8192
#define F_W2   8192       // W2 [64][64]             4096
#define F_H1   12288      // h1 [200][68]           13600
#define F_QC   25888      // qc[64]
#define F_B2   25952      // b2[64]
#define F_W3   26016      // W3[64]
#define F_SC   26080      // scores/att [256]
#define F_RED  26336      // softmax scratch [32]
#define F_OUT  26368      // out partials [4][128]
#define SMEM_FLOATS 26880
#define SMEM_BYTES  (SMEM_FLOATS * 4)   // 107520 B -> 2 CTAs/SM
#define H1S 68            // h1 row stride (floats)

// =============== prep: per-batch Wc + qc (grid B, 256 thr) ===============
extern "C" __global__ void __launch_bounds__(256)
din_prep(const float* __restrict__ query,
         const float* __restrict__ W1,
         const float* __restrict__ b1) {
    __shared__ float q[DD];
    __shared__ float qp[4][64];
    const int t = threadIdx.x;
    const int b = blockIdx.x;
    if (t < DD) q[t] = query[b * DD + t];
    __syncthreads();

    float* out = g_Wc + (size_t)b * 8192;
    for (int i = t; i < 8192; i += 256) {
        int d = i >> 6, c = i & 63;
        out[i] = W1[(DD + d) * AA + c] - W1[(2 * DD + d) * AA + c]
               + q[d] * W1[(3 * DD + d) * AA + c];
    }
    {   // qc[a] = b1[a] + sum_d q[d]*(W1a+W1c)[d][a]
        int a = t & 63, seg = t >> 6;
        float s = 0.f;
        for (int d = seg * 32; d < seg * 32 + 32; d++)
            s += q[d] * (W1[d * AA + a] + W1[(2 * DD + d) * AA + a]);
        qp[seg][a] = s;
    }
    __syncthreads();
    if (t < 64)
        g_qc[(size_t)b * 64 + t] = b1[t] + qp[0][t] + qp[1][t] + qp[2][t] + qp[3][t];
}

// =============== main fused kernel (grid B, 512 thr, 2 CTAs/SM) ===============
extern "C" __global__ void __launch_bounds__(512, 2)
din_main(const float* __restrict__ keys,
         const int*   __restrict__ klen,
         const float* __restrict__ W2,
         const float* __restrict__ b2,
         const float* __restrict__ a1p,
         const float* __restrict__ a2p,
         const float* __restrict__ W3,
         const float* __restrict__ b3p,
         float* __restrict__ outp,
         float* __restrict__ attp)
{
    extern __shared__ float sm[];
    const int t    = threadIdx.x;
    const int b    = blockIdx.x;
    const int lg   = t >> 2;               // 0..127, busy if < 100
    const int cg   = t & 3;                // c = 16k + 4cg + j
    const int lgc  = (lg < 100) ? lg : 99;
    const int r0   = 2 * lgc;
    const int lane = t & 31;
    const int w    = t >> 5;

    const float pa1 = a1p[0], pa2 = a2p[0], b3v = b3p[0];
    const int   len = klen[b];

    // ---- setup: stream Wc, W2, qc/b2/W3 ----
    {
        const float4* Wg = (const float4*)(g_Wc + (size_t)b * 8192);
        float4* Ws = (float4*)(sm + F_WC);
        for (int i = t; i < 2048; i += 512) Ws[i] = Wg[i];
        const float4* W2g = (const float4*)W2;
        float4* W2s = (float4*)(sm + F_W2);
        for (int i = t; i < 1024; i += 512) W2s[i] = W2g[i];
        if (t < 64) sm[F_QC + t] = g_qc[(size_t)b * 64 + t];
        else if (t < 128) sm[F_B2 + (t - 64)] = b2[t - 64];
        else if (t < 192) sm[F_W3 + (t - 128)] = W3[t - 128];
    }
    __syncthreads();

    const float4* Kg = (const float4*)(keys + (size_t)b * LL * DD);

    // ==== GEMM1: acc[li][2k+h] = c-pair (16k+4cg+2h, +1), rows r0/r0+1 ====
    {
        ull acc[2][8];
        {
            const ull* qcp = (const ull*)(sm + F_QC);
            #pragma unroll
            for (int k = 0; k < 4; k++) {
                acc[0][2*k]   = qcp[8*k + 2*cg];
                acc[0][2*k+1] = qcp[8*k + 2*cg + 1];
                acc[1][2*k]   = acc[0][2*k];
                acc[1][2*k+1] = acc[0][2*k+1];
            }
        }
        #pragma unroll 1
        for (int d4 = 0; d4 < 32; d4 += 2) {    // 32B sector pair per row
            float4 ka0 = __ldg(Kg + r0 * 32 + d4);
            float4 kb0 = __ldg(Kg + (r0 + 1) * 32 + d4);
            float4 ka1 = __ldg(Kg + r0 * 32 + d4 + 1);
            float4 kb1 = __ldg(Kg + (r0 + 1) * 32 + d4 + 1);
            #pragma unroll
            for (int hh = 0; hh < 2; hh++) {
                float4 ka = hh ? ka1 : ka0;
                float4 kb = hh ? kb1 : kb0;
                int db = (d4 + hh) * 4;
                #pragma unroll
                for (int dd = 0; dd < 4; dd++) {
                    float kda = (dd == 0) ? ka.x : (dd == 1) ? ka.y : (dd == 2) ? ka.z : ka.w;
                    float kdb = (dd == 0) ? kb.x : (dd == 1) ? kb.y : (dd == 2) ? kb.z : kb.w;
                    ull pa = pk2(kda, kda), pb = pk2(kdb, kdb);
                    const ulonglong2* wr = (const ulonglong2*)(sm + F_WC + (db + dd) * 64);
                    #pragma unroll
                    for (int k = 0; k < 4; k++) {
                        ulonglong2 wv = wr[4 * k + cg];
                        acc[0][2*k]   = ffma2(pa, wv.x, acc[0][2*k]);
                        acc[0][2*k+1] = ffma2(pa, wv.y, acc[0][2*k+1]);
                        acc[1][2*k]   = ffma2(pb, wv.x, acc[1][2*k]);
                        acc[1][2*k+1] = ffma2(pb, wv.y, acc[1][2*k+1]);
                    }
                }
            }
        }
        // prelu(a1) -> h1 rows r0, r0+1 (qc already folded into init)
        #pragma unroll
        for (int li = 0; li < 2; li++) {
            #pragma unroll
            for (int k = 0; k < 4; k++) {
                float v0, v1, v2, v3;
                upk2(acc[li][2*k],   v0, v1);
                upk2(acc[li][2*k+1], v2, v3);
                v0 = (v0 >= 0.f) ? v0 : pa1 * v0;
                v1 = (v1 >= 0.f) ? v1 : pa1 * v1;
                v2 = (v2 >= 0.f) ? v2 : pa1 * v2;
                v3 = (v3 >= 0.f) ? v3 : pa1 * v3;
                if (lg < 100)
                    *(float4*)(sm + F_H1 + (r0 + li) * H1S + 16 * k + 4 * cg) =
                        make_float4(v0, v1, v2, v3);
            }
        }
    }
    __syncthreads();

    // ==== GEMM2: h2 rows r0/r0+1 over all 64 a ====
    float s0 = 0.f, s1 = 0.f;
    {
        ull acc[2][8];
        {
            const ull* bp = (const ull*)(sm + F_B2);
            #pragma unroll
            for (int k = 0; k < 4; k++) {
                acc[0][2*k]   = bp[8*k + 2*cg];
                acc[0][2*k+1] = bp[8*k + 2*cg + 1];
                acc[1][2*k]   = acc[0][2*k];
                acc[1][2*k+1] = acc[0][2*k+1];
            }
        }
        #pragma unroll 1
        for (int m = 0; m < 16; m++) {         // a = 4m..4m+3
            float4 h0 = *(const float4*)(sm + F_H1 + r0 * H1S + 4 * m);
            float4 h1 = *(const float4*)(sm + F_H1 + (r0 + 1) * H1S + 4 * m);
            #pragma unroll
            for (int aa = 0; aa < 4; aa++) {
                float ha = (aa == 0) ? h0.x : (aa == 1) ? h0.y : (aa == 2) ? h0.z : h0.w;
                float hb = (aa == 0) ? h1.x : (aa == 1) ? h1.y : (aa == 2) ? h1.z : h1.w;
                ull pa = pk2(ha, ha), pb = pk2(hb, hb);
                const ulonglong2* wr = (const ulonglong2*)(sm + F_W2 + (4 * m + aa) * 64);
                #pragma unroll
                for (int k = 0; k < 4; k++) {
                    ulonglong2 wv = wr[4 * k + cg];
                    acc[0][2*k]   = ffma2(pa, wv.x, acc[0][2*k]);
                    acc[0][2*k+1] = ffma2(pa, wv.y, acc[0][2*k+1]);
                    acc[1][2*k]   = ffma2(pb, wv.x, acc[1][2*k]);
                    acc[1][2*k+1] = ffma2(pb, wv.y, acc[1][2*k+1]);
                }
            }
        }
        // prelu(a2) + W3 dot
        #pragma unroll
        for (int li = 0; li < 2; li++) {
            float s = 0.f;
            #pragma unroll
            for (int k = 0; k < 4; k++) {
                float2 w3a = *(const float2*)(sm + F_W3 + 16 * k + 4 * cg);
                float2 w3b = *(const float2*)(sm + F_W3 + 16 * k + 4 * cg + 2);
                float v0, v1, v2, v3;
                upk2(acc[li][2*k],   v0, v1);
                upk2(acc[li][2*k+1], v2, v3);
                v0 = (v0 >= 0.f) ? v0 : pa2 * v0;
                v1 = (v1 >= 0.f) ? v1 : pa2 * v1;
                v2 = (v2 >= 0.f) ? v2 : pa2 * v2;
                v3 = (v3 >= 0.f) ? v3 : pa2 * v3;
                s += v0 * w3a.x + v1 * w3a.y + v2 * w3b.x + v3 * w3b.y;
            }
            if (li == 0) s0 = s; else s1 = s;
        }
    }
    // reduce over 4 cg lanes (lane bits 0-1)
    s0 += __shfl_xor_sync(0xffffffffu, s0, 1);
    s0 += __shfl_xor_sync(0xffffffffu, s0, 2);
    s1 += __shfl_xor_sync(0xffffffffu, s1, 1);
    s1 += __shfl_xor_sync(0xffffffffu, s1, 2);
    if (lg < 100 && cg == 0) {
        sm[F_SC + r0]     = (r0 < len)     ? (s0 + b3v) : NEGINF;
        sm[F_SC + r0 + 1] = (r0 + 1 < len) ? (s1 + b3v) : NEGINF;
    }
    if (t >= 400 && t < 456) sm[F_SC + (t - 200)] = FNEGINF;  // pads 200..255
    __syncthreads();

    // ---- softmax over 256 slots ----
    float v = 0.f, e = 0.f;
    if (t < 256) {
        v = sm[F_SC + t];
        float m = v;
        #pragma unroll
        for (int o = 16; o > 0; o >>= 1) m = fmaxf(m, __shfl_xor_sync(0xffffffffu, m, o));
        if (lane == 0) sm[F_RED + w] = m;
    }
    __syncthreads();
    if (t == 0) {
        float mm = sm[F_RED];
        for (int i = 1; i < 8; i++) mm = fmaxf(mm, sm[F_RED + i]);
        sm[F_RED + 8] = mm;
    }
    __syncthreads();
    if (t < 256) {
        float M = sm[F_RED + 8];
        e = (t < LL) ? __expf(v - M) : 0.f;
        float ss = e;
        #pragma unroll
        for (int o = 16; o > 0; o >>= 1) ss += __shfl_xor_sync(0xffffffffu, ss, o);
        if (lane == 0) sm[F_RED + 16 + w] = ss;
    }
    __syncthreads();
    if (t == 0) {
        float s = 0.f;
        for (int i = 0; i < 8; i++) s += sm[F_RED + 16 + i];
        sm[F_RED + 24] = s;
    }
    __syncthreads();
    if (t < LL) {
        float at = e / sm[F_RED + 24];
        sm[F_SC + t] = at;
        attp[(size_t)b * LL + t] = at;
    }
    __syncthreads();

    // ---- out[b][d] = sum_l att[l]*K[l][d], 4-way l split, coalesced LDG ----
    {
        int d = t & 127, seg = t >> 7;
        const float* Kp = keys + ((size_t)b * LL + seg * 50) * DD + d;
        const float* Ap = sm + F_SC + seg * 50;
        float a0 = 0.f, a1 = 0.f;
        #pragma unroll 5
        for (int l = 0; l < 50; l += 2) {
            a0 += Ap[l]     * Kp[l * DD];
            a1 += Ap[l + 1] * Kp[(l + 1) * DD];
        }
        sm[F_OUT + seg * 128 + d] = a0 + a1;
    }
    __syncthreads();
    if (t < DD) {
        outp[(size_t)b * DD + t] = (sm[F_OUT + t] + sm[F_OUT + 128 + t])
                                 + (sm[F_OUT + 256 + t] + sm[F_OUT + 384 + t]);
    }
}

extern "C" void kernel_launch(void* const* d_in, const int* in_sizes, int n_in,
                              void* d_out, int out_size) {
    const float* query = (const float*)d_in[0];
    const float* keys  = (const float*)d_in[1];
    const int*   klen  = (const int*)  d_in[2];
    const float* W1    = (const float*)d_in[3];
    const float* b1    = (const float*)d_in[4];
    const float* a1    = (const float*)d_in[5];
    const float* W2    = (const float*)d_in[6];
    const float* b2    = (const float*)d_in[7];
    const float* a2    = (const float*)d_in[8];
    const float* W3    = (const float*)d_in[9];
    const float* b3    = (const float*)d_in[10];

    int Bn = in_sizes[0] / DD;  // 2048
    float* outp = (float*)d_out;               // (B, D)
    float* attp = outp + (size_t)Bn * DD;      // (B, L)

    din_prep<<<Bn, 256>>>(query, W1, b1);
    cudaFuncSetAttribute(din_main,
                         cudaFuncAttributeMaxDynamicSharedMemorySize, SMEM_BYTES);
    din_main<<<Bn, 512, SMEM_BYTES>>>(
        keys, klen, W2, b2, a1, a2, W3, b3, outp, attp);
}

// round 17
// speedup vs baseline: 1.2931x; 1.2931x over previous
#include <cuda_runtime.h>
#include <cstdint>

// Fixed shapes: B=2048, L=200, D=128, A=64
#define DD 128
#define AA 64
#define LL 200
#define BB 2048
#define NEGINF (-4294967295.0f)
#define FNEGINF __int_as_float(0xff800000)

typedef unsigned long long ull;

__device__ __forceinline__ ull pk2(float lo, float hi) {
    ull r; asm("mov.b64 %0,{%1,%2};" : "=l"(r) : "f"(lo), "f"(hi)); return r;
}
__device__ __forceinline__ void upk2(ull v, float& lo, float& hi) {
    asm("mov.b64 {%0,%1},%2;" : "=f"(lo), "=f"(hi) : "l"(v));
}
__device__ __forceinline__ ull ffma2(ull a, ull b, ull c) {
    ull d; asm("fma.rn.f32x2 %0,%1,%2,%3;" : "=l"(d) : "l"(a), "l"(b), "l"(c)); return d;
}

// ---- device scratch (module-load allocation; no runtime alloc) ----
__device__ float g_Wc[(size_t)BB * 8192];   // per-batch combined W1 [128][64]
__device__ float g_qc[(size_t)BB * 64];     // per-batch qc (b1 + q-part)

// ---- din_main smem (float offsets); phase-overlapped ----
#define F_WC   0          // phase1: Wc [128][64] (8192)
#define F_H1   0          // phase2: h1 [200] stride 68, granule-XOR (13600)
#define F_K0   13600      // K chunk buf0 [200][20] (4000)
#define F_K1   17600      // K chunk buf1 (4000)
#define F_W2   13600      // phase2: W2 [64][64] (4096), over buf0
#define F_QC   21600
#define F_B2   21664
#define F_W3   21728
#define F_SC   21792      // scores/att [256]
#define F_RED  22048      // [32]
#define F_OUT  22080      // [4][128]
#define SMEM_FLOATS 22592
#define SMEM_BYTES  (SMEM_FLOATS * 4)   // 90368 B -> 2 CTAs/SM
#define H1S 68

// =============== prep: per-batch Wc + qc (grid B, 256 thr) ===============
extern "C" __global__ void __launch_bounds__(256)
din_prep(const float* __restrict__ query,
         const float* __restrict__ W1,
         const float* __restrict__ b1) {
    __shared__ float q[DD];
    __shared__ float qp[4][64];
    const int t = threadIdx.x;
    const int b = blockIdx.x;
    if (t < DD) q[t] = query[b * DD + t];
    __syncthreads();

    float* out = g_Wc + (size_t)b * 8192;
    for (int i = t; i < 8192; i += 256) {
        int d = i >> 6, c = i & 63;
        out[i] = W1[(DD + d) * AA + c] - W1[(2 * DD + d) * AA + c]
               + q[d] * W1[(3 * DD + d) * AA + c];
    }
    {
        int a = t & 63, seg = t >> 6;
        float s = 0.f;
        for (int d = seg * 32; d < seg * 32 + 32; d++)
            s += q[d] * (W1[d * AA + a] + W1[(2 * DD + d) * AA + a]);
        qp[seg][a] = s;
    }
    __syncthreads();
    if (t < 64)
        g_qc[(size_t)b * 64 + t] = b1[t] + qp[0][t] + qp[1][t] + qp[2][t] + qp[3][t];
}

// =============== main fused kernel (grid B, 512 thr, 2 CTAs/SM) ===============
extern "C" __global__ void __launch_bounds__(512, 2)
din_main(const float* __restrict__ keys,
         const int*   __restrict__ klen,
         const float* __restrict__ W2,
         const float* __restrict__ b2,
         const float* __restrict__ a1p,
         const float* __restrict__ a2p,
         const float* __restrict__ W3,
         const float* __restrict__ b3p,
         float* __restrict__ outp,
         float* __restrict__ attp)
{
    extern __shared__ float sm[];
    const int t    = threadIdx.x;
    const int b    = blockIdx.x;
    const int lg   = t >> 3;               // 0..63, busy if < 50
    const int cg   = t & 7;
    const int lgc  = (lg < 50) ? lg : 49;
    const int r0   = 4 * lgc;              // 4 rows per thread
    const int sk   = lgc & 3;              // granule-XOR key (rows share r>>2)
    const int lane = t & 31;
    const int w    = t >> 5;
    const int cA   = 4 * cg;               // columns 4cg..4cg+3   (granule cg)
    const int cB   = 32 + 4 * cg;          // columns 32+4cg..+3   (granule 8+cg)

    const float pa1 = a1p[0], pa2 = a2p[0], b3v = b3p[0];
    const int   len = klen[b];

    const float4* Kg4 = (const float4*)(keys + (size_t)b * LL * DD);

    // ---- setup: stream Wc; misc scalars ----
    {
        const float4* Wg = (const float4*)(g_Wc + (size_t)b * 8192);
        float4* Ws = (float4*)(sm + F_WC);
        for (int i = t; i < 2048; i += 512) Ws[i] = Wg[i];
        if (t < 64) sm[F_QC + t] = g_qc[(size_t)b * 64 + t];
        else if (t < 128) sm[F_B2 + (t - 64)] = b2[t - 64];
        else if (t < 192) sm[F_W3 + (t - 128)] = W3[t - 128];
    }

    // ---- K chunk fill helper: chunk ch = d [16ch,16ch+16), swizzled stride-20 ----
    #define FILL_CHUNK(ch, base)                                                  \
    {                                                                             \
        _Pragma("unroll")                                                         \
        for (int rep = 0; rep < 2; rep++) {                                       \
            int i = t + rep * 512;                                                \
            if (i < 800) {                                                        \
                int row = i >> 2, jg = i & 3;                                     \
                float4 v = __ldg(Kg4 + row * 32 + (ch) * 4 + jg);                 \
                *(float4*)(sm + (base) + row * 20 + 4 * (jg ^ ((row >> 2) & 3)))  \
                    = v;                                                          \
            }                                                                     \
        }                                                                         \
    }

    FILL_CHUNK(0, F_K0);
    __syncthreads();

    // ==== GEMM1: acc[ri][p] : rows r0+ri, cols cA(p0,1) cB(p2,3) ====
    ull acc[4][4];
    {
        const ull* qa = (const ull*)(sm + F_QC + cA);
        const ull* qb = (const ull*)(sm + F_QC + cB);
        #pragma unroll
        for (int ri = 0; ri < 4; ri++) {
            acc[ri][0] = qa[0]; acc[ri][1] = qa[1];
            acc[ri][2] = qb[0]; acc[ri][3] = qb[1];
        }
    }
    #pragma unroll 1
    for (int ch = 0; ch < 8; ch++) {
        const int cur = (ch & 1) ? F_K1 : F_K0;
        if (ch < 7) FILL_CHUNK(ch + 1, (ch & 1) ? F_K0 : F_K1);
        #pragma unroll
        for (int jg = 0; jg < 4; jg++) {
            float4 kv[4];
            #pragma unroll
            for (int ri = 0; ri < 4; ri++)
                kv[ri] = *(const float4*)(sm + cur + (r0 + ri) * 20 + 4 * (jg ^ sk));
            #pragma unroll
            for (int dd = 0; dd < 4; dd++) {
                const int d = ch * 16 + jg * 4 + dd;
                ulonglong2 wa = *(const ulonglong2*)(sm + F_WC + d * 64 + cA);
                ulonglong2 wb = *(const ulonglong2*)(sm + F_WC + d * 64 + cB);
                #pragma unroll
                for (int ri = 0; ri < 4; ri++) {
                    float kd = (dd == 0) ? kv[ri].x : (dd == 1) ? kv[ri].y
                             : (dd == 2) ? kv[ri].z : kv[ri].w;
                    ull kp = pk2(kd, kd);
                    acc[ri][0] = ffma2(kp, wa.x, acc[ri][0]);
                    acc[ri][1] = ffma2(kp, wa.y, acc[ri][1]);
                    acc[ri][2] = ffma2(kp, wb.x, acc[ri][2]);
                    acc[ri][3] = ffma2(kp, wb.y, acc[ri][3]);
                }
            }
        }
        __syncthreads();
    }

    // ---- phase switch: h1 (over Wc) + W2 (over K buf0) ----
    if (lg < 50) {
        #pragma unroll
        for (int ri = 0; ri < 4; ri++) {
            float v0, v1, v2, v3;
            upk2(acc[ri][0], v0, v1); upk2(acc[ri][1], v2, v3);
            v0 = (v0 >= 0.f) ? v0 : pa1 * v0;
            v1 = (v1 >= 0.f) ? v1 : pa1 * v1;
            v2 = (v2 >= 0.f) ? v2 : pa1 * v2;
            v3 = (v3 >= 0.f) ? v3 : pa1 * v3;
            *(float4*)(sm + F_H1 + (r0 + ri) * H1S + 4 * (cg ^ sk)) =
                make_float4(v0, v1, v2, v3);
            upk2(acc[ri][2], v0, v1); upk2(acc[ri][3], v2, v3);
            v0 = (v0 >= 0.f) ? v0 : pa1 * v0;
            v1 = (v1 >= 0.f) ? v1 : pa1 * v1;
            v2 = (v2 >= 0.f) ? v2 : pa1 * v2;
            v3 = (v3 >= 0.f) ? v3 : pa1 * v3;
            *(float4*)(sm + F_H1 + (r0 + ri) * H1S + 32 + 4 * (cg ^ sk)) =
                make_float4(v0, v1, v2, v3);
        }
    }
    {
        const float4* W2g = (const float4*)W2;
        float4* W2s = (float4*)(sm + F_W2);
        for (int i = t; i < 1024; i += 512) W2s[i] = W2g[i];
    }
    __syncthreads();

    // ==== GEMM2: rows r0..r0+3 over all 64 a ====
    float s0 = 0.f, s1 = 0.f, s2 = 0.f, s3 = 0.f;
    {
        ull acc2[4][4];
        {
            const ull* ba = (const ull*)(sm + F_B2 + cA);
            const ull* bb = (const ull*)(sm + F_B2 + cB);
            #pragma unroll
            for (int ri = 0; ri < 4; ri++) {
                acc2[ri][0] = ba[0]; acc2[ri][1] = ba[1];
                acc2[ri][2] = bb[0]; acc2[ri][3] = bb[1];
            }
        }
        #pragma unroll 1
        for (int m = 0; m < 16; m++) {       // logical a-granule m: a = 4m..4m+3
            float4 hq[4];
            #pragma unroll
            for (int ri = 0; ri < 4; ri++)
                hq[ri] = *(const float4*)(sm + F_H1 + (r0 + ri) * H1S + 4 * (m ^ sk));
            #pragma unroll
            for (int aa = 0; aa < 4; aa++) {
                const int a = 4 * m + aa;
                ulonglong2 wa = *(const ulonglong2*)(sm + F_W2 + a * 64 + cA);
                ulonglong2 wb = *(const ulonglong2*)(sm + F_W2 + a * 64 + cB);
                #pragma unroll
                for (int ri = 0; ri < 4; ri++) {
                    float hd = (aa == 0) ? hq[ri].x : (aa == 1) ? hq[ri].y
                             : (aa == 2) ? hq[ri].z : hq[ri].w;
                    ull hp = pk2(hd, hd);
                    acc2[ri][0] = ffma2(hp, wa.x, acc2[ri][0]);
                    acc2[ri][1] = ffma2(hp, wa.y, acc2[ri][1]);
                    acc2[ri][2] = ffma2(hp, wb.x, acc2[ri][2]);
                    acc2[ri][3] = ffma2(hp, wb.y, acc2[ri][3]);
                }
            }
        }
        // prelu(a2) + W3 dot
        float2 w3a0 = *(const float2*)(sm + F_W3 + cA);
        float2 w3a1 = *(const float2*)(sm + F_W3 + cA + 2);
        float2 w3b0 = *(const float2*)(sm + F_W3 + cB);
        float2 w3b1 = *(const float2*)(sm + F_W3 + cB + 2);
        float ps[4];
        #pragma unroll
        for (int ri = 0; ri < 4; ri++) {
            float s = 0.f, lo, hi;
            upk2(acc2[ri][0], lo, hi);
            lo = (lo >= 0.f) ? lo : pa2 * lo;  hi = (hi >= 0.f) ? hi : pa2 * hi;
            s += lo * w3a0.x + hi * w3a0.y;
            upk2(acc2[ri][1], lo, hi);
            lo = (lo >= 0.f) ? lo : pa2 * lo;  hi = (hi >= 0.f) ? hi : pa2 * hi;
            s += lo * w3a1.x + hi * w3a1.y;
            upk2(acc2[ri][2], lo, hi);
            lo = (lo >= 0.f) ? lo : pa2 * lo;  hi = (hi >= 0.f) ? hi : pa2 * hi;
            s += lo * w3b0.x + hi * w3b0.y;
            upk2(acc2[ri][3], lo, hi);
            lo = (lo >= 0.f) ? lo : pa2 * lo;  hi = (hi >= 0.f) ? hi : pa2 * hi;
            s += lo * w3b1.x + hi * w3b1.y;
            ps[ri] = s;
        }
        s0 = ps[0]; s1 = ps[1]; s2 = ps[2]; s3 = ps[3];
    }
    // reduce over 8 cg lanes (lane bits 0-2)
    #pragma unroll
    for (int o = 4; o > 0; o >>= 1) {
        s0 += __shfl_xor_sync(0xffffffffu, s0, o);
        s1 += __shfl_xor_sync(0xffffffffu, s1, o);
        s2 += __shfl_xor_sync(0xffffffffu, s2, o);
        s3 += __shfl_xor_sync(0xffffffffu, s3, o);
    }
    if (lg < 50 && cg == 0) {
        float sc[4] = {s0, s1, s2, s3};
        #pragma unroll
        for (int ri = 0; ri < 4; ri++) {
            int l = r0 + ri;
            sm[F_SC + l] = (l < len) ? (sc[ri] + b3v) : NEGINF;
        }
    }
    if (t >= 400 && t < 456) sm[F_SC + (t - 200)] = FNEGINF;
    __syncthreads();

    // ---- softmax over 256 slots ----
    float v = 0.f, e = 0.f;
    if (t < 256) {
        v = sm[F_SC + t];
        float m = v;
        #pragma unroll
        for (int o = 16; o > 0; o >>= 1) m = fmaxf(m, __shfl_xor_sync(0xffffffffu, m, o));
        if (lane == 0) sm[F_RED + w] = m;
    }
    __syncthreads();
    if (t == 0) {
        float mm = sm[F_RED];
        for (int i = 1; i < 8; i++) mm = fmaxf(mm, sm[F_RED + i]);
        sm[F_RED + 8] = mm;
    }
    __syncthreads();
    if (t < 256) {
        float M = sm[F_RED + 8];
        e = (t < LL) ? __expf(v - M) : 0.f;
        float ss = e;
        #pragma unroll
        for (int o = 16; o > 0; o >>= 1) ss += __shfl_xor_sync(0xffffffffu, ss, o);
        if (lane == 0) sm[F_RED + 16 + w] = ss;
    }
    __syncthreads();
    if (t == 0) {
        float s = 0.f;
        for (int i = 0; i < 8; i++) s += sm[F_RED + 16 + i];
        sm[F_RED + 24] = s;
    }
    __syncthreads();
    if (t < LL) {
        float at = e / sm[F_RED + 24];
        sm[F_SC + t] = at;
        attp[(size_t)b * LL + t] = at;
    }
    __syncthreads();

    // ---- out[b][d] = sum_l att[l]*K[l][d], 4-way l split, coalesced LDG ----
    {
        int d = t & 127, seg = t >> 7;
        const float* Kp = keys + ((size_t)b * LL + seg * 50) * DD + d;
        const float* Ap = sm + F_SC + seg * 50;
        float a0 = 0.f, a1 = 0.f;
        #pragma unroll 5
        for (int l = 0; l < 50; l += 2) {
            a0 += Ap[l]     * Kp[l * DD];
            a1 += Ap[l + 1] * Kp[(l + 1) * DD];
        }
        sm[F_OUT + seg * 128 + d] = a0 + a1;
    }
    __syncthreads();
    if (t < DD) {
        outp[(size_t)b * DD + t] = (sm[F_OUT + t] + sm[F_OUT + 128 + t])
                                 + (sm[F_OUT + 256 + t] + sm[F_OUT + 384 + t]);
    }
}

extern "C" void kernel_launch(void* const* d_in, const int* in_sizes, int n_in,
                              void* d_out, int out_size) {
    const float* query = (const float*)d_in[0];
    const float* keys  = (const float*)d_in[1];
    const int*   klen  = (const int*)  d_in[2];
    const float* W1    = (const float*)d_in[3];
    const float* b1    = (const float*)d_in[4];
    const float* a1    = (const float*)d_in[5];
    const float* W2    = (const float*)d_in[6];
    const float* b2    = (const float*)d_in[7];
    const float* a2    = (const float*)d_in[8];
    const float* W3    = (const float*)d_in[9];
    const float* b3    = (const float*)d_in[10];

    int Bn = in_sizes[0] / DD;  // 2048
    float* outp = (float*)d_out;               // (B, D)
    float* attp = outp + (size_t)Bn * DD;      // (B, L)

    din_prep<<<Bn, 256>>>(query, W1, b1);
    cudaFuncSetAttribute(din_main,
                         cudaFuncAttributeMaxDynamicSharedMemorySize, SMEM_BYTES);
    din_main<<<Bn, 512, SMEM_BYTES>>>(
        keys, klen, W2, b2, a1, a2, W3, b3, outp, attp);
}